// round 1
// baseline (speedup 1.0000x reference)
#include <cuda_runtime.h>
#include <cuda_bf16.h>
#include <cstdint>
#include <cstdio>

// ---------------- problem constants ----------------
#define N_NODES 50000
#define N_EDGES 1600000
#define E_TOT   (N_EDGES + N_NODES)   // + self loops
#define F_IN    128

// ---------------- device scratch (static: no allocations allowed) ----------------
__device__ float g_h[(size_t)N_NODES * 240];    // transformed features per layer
__device__ float g_agg[(size_t)N_NODES * 240];  // aggregated output per layer
__device__ float g_als[(size_t)N_NODES * 6];
__device__ float g_ald[(size_t)N_NODES * 6];
__device__ int   g_counts[N_NODES];
__device__ int   g_cursor[N_NODES];
__device__ int   g_offsets[N_NODES + 1];
__device__ int   g_csr[E_TOT];
__device__ int   g_idx64;   // 1 if edge_index is int64, 0 if int32

// ---------------- small utility kernels ----------------
__global__ void zero_int_kernel(int* a, int n) {
    int i = blockIdx.x * blockDim.x + threadIdx.x;
    if (i < n) a[i] = 0;
}

__global__ void detect_idx_kernel(const int* p) {
    if (blockIdx.x == 0 && threadIdx.x == 0) {
        int all0 = 1;
        #pragma unroll 1
        for (int i = 0; i < 128; i++) {
            if (p[2 * i + 1] != 0) { all0 = 0; break; }
        }
        g_idx64 = all0;
    }
}

__device__ __forceinline__ void load_edge(const void* ei, int i, int& src, int& dst) {
    if (i < N_EDGES) {
        if (g_idx64) {
            const long long* q = (const long long*)ei;
            src = (int)q[i];
            dst = (int)q[(size_t)N_EDGES + i];
        } else {
            const int* q = (const int*)ei;
            src = q[i];
            dst = q[N_EDGES + i];
        }
    } else {
        src = dst = i - N_EDGES;  // self loop
    }
}

__global__ void count_kernel(const void* ei) {
    int i = blockIdx.x * blockDim.x + threadIdx.x;
    if (i >= E_TOT) return;
    int src, dst;
    load_edge(ei, i, src, dst);
    atomicAdd(&g_counts[dst], 1);
}

__global__ void scan_kernel() {
    __shared__ int tsum[1024];
    const int CH = (N_NODES + 1023) / 1024;  // 49
    int tid = threadIdx.x;
    int base = tid * CH;
    int s = 0;
    for (int i = 0; i < CH; i++) {
        int idx = base + i;
        if (idx < N_NODES) s += g_counts[idx];
    }
    tsum[tid] = s;
    __syncthreads();
    for (int off = 1; off < 1024; off <<= 1) {
        int v = (tid >= off) ? tsum[tid - off] : 0;
        __syncthreads();
        tsum[tid] += v;
        __syncthreads();
    }
    int excl = tsum[tid] - s;
    for (int i = 0; i < CH; i++) {
        int idx = base + i;
        if (idx < N_NODES) {
            g_offsets[idx] = excl;
            excl += g_counts[idx];
        }
    }
    if (tid == 1023) g_offsets[N_NODES] = tsum[1023];
}

__global__ void fill_kernel(const void* ei) {
    int i = blockIdx.x * blockDim.x + threadIdx.x;
    if (i >= E_TOT) return;
    int src, dst;
    load_edge(ei, i, src, dst);
    int p = atomicAdd(&g_cursor[dst], 1);
    g_csr[g_offsets[dst] + p] = src;
}

// ---------------- fused GEMM + attention-logit kernel ----------------
// h = X @ W  (X:[N,K], W:[K,F]) ; als[n][h] = sum_c h[n,h*C+c]*a_s[h*C+c] ; same ald.
template <int K, int F, int BM, int TM, int TF, int H>
__global__ void gemm_al_kernel(const float* __restrict__ X, const float* __restrict__ W,
                               const float* __restrict__ Avs, const float* __restrict__ Avd,
                               float* __restrict__ Ho, float* __restrict__ als,
                               float* __restrict__ ald, int Nn) {
    constexpr int MTH = BM / TM;
    constexpr int FTH = F / TF;
    constexpr int NTH = MTH * FTH;
    constexpr int C = F / H;
    constexpr int XLD = K + 1;
    extern __shared__ float sh[];
    float* ws = sh;                  // K*F
    float* xs = ws + K * F;          // BM*XLD
    float* asum = xs + BM * XLD;     // BM*2*H

    int tid = threadIdx.x;
    for (int i = tid; i < K * F; i += NTH) ws[i] = W[i];

    int mx = tid % MTH;
    int fx = tid / MTH;
    int f0 = fx * TF;
    int headT = f0 / C;
    float ras[TF], rad[TF];
    #pragma unroll
    for (int j = 0; j < TF; j++) { ras[j] = Avs[f0 + j]; rad[j] = Avd[f0 + j]; }

    for (int tile = blockIdx.x * BM; tile < Nn; tile += gridDim.x * BM) {
        __syncthreads();
        for (int i = tid; i < BM * K; i += NTH) {
            int m = i / K, k = i - m * K;
            int gm = tile + m;
            xs[m * XLD + k] = (gm < Nn) ? X[(size_t)gm * K + k] : 0.f;
        }
        for (int i = tid; i < BM * 2 * H; i += NTH) asum[i] = 0.f;
        __syncthreads();

        float acc[TM][TF];
        #pragma unroll
        for (int i = 0; i < TM; i++)
            #pragma unroll
            for (int j = 0; j < TF; j++) acc[i][j] = 0.f;

        #pragma unroll 4
        for (int k = 0; k < K; k++) {
            float xv[TM];
            #pragma unroll
            for (int i = 0; i < TM; i++) xv[i] = xs[(mx + i * MTH) * XLD + k];
            float wv[TF];
            #pragma unroll
            for (int j4 = 0; j4 < TF / 4; j4++) {
                float4 w4 = *reinterpret_cast<const float4*>(&ws[k * F + f0 + j4 * 4]);
                wv[j4 * 4 + 0] = w4.x; wv[j4 * 4 + 1] = w4.y;
                wv[j4 * 4 + 2] = w4.z; wv[j4 * 4 + 3] = w4.w;
            }
            #pragma unroll
            for (int i = 0; i < TM; i++)
                #pragma unroll
                for (int j = 0; j < TF; j++) acc[i][j] = fmaf(xv[i], wv[j], acc[i][j]);
        }

        #pragma unroll
        for (int i = 0; i < TM; i++) {
            int m = mx + i * MTH;
            int gm = tile + m;
            if (gm < Nn) {
                float ss = 0.f, sd = 0.f;
                #pragma unroll
                for (int j = 0; j < TF; j++) {
                    Ho[(size_t)gm * F + f0 + j] = acc[i][j];
                    ss += acc[i][j] * ras[j];
                    sd += acc[i][j] * rad[j];
                }
                atomicAdd(&asum[m * 2 * H + headT], ss);
                atomicAdd(&asum[m * 2 * H + H + headT], sd);
            }
        }
        __syncthreads();
        for (int i = tid; i < BM * H; i += NTH) {
            int m = i / H, hh = i - m * H;
            int gm = tile + m;
            if (gm < Nn) {
                als[gm * H + hh] = asum[m * 2 * H + hh];
                ald[gm * H + hh] = asum[m * 2 * H + H + hh];
            }
        }
    }
}

// ---------------- per-dst softmax aggregation: one warp per node ----------------
template <int H, int C, bool FUSE_BIAS_ELU>
__global__ void agg_kernel(const float* __restrict__ h, const float* __restrict__ als,
                           const float* __restrict__ ald, const float* __restrict__ bias,
                           float* __restrict__ out) {
    constexpr int F = H * C;
    constexpr int RPL = (F + 31) / 32;
    int gw = (blockIdx.x * blockDim.x + threadIdx.x) >> 5;
    if (gw >= N_NODES) return;
    int lane = threadIdx.x & 31;
    int beg = g_offsets[gw], end = g_offsets[gw + 1];

    float aldh[H];
    #pragma unroll
    for (int hh = 0; hh < H; hh++) aldh[hh] = ald[gw * H + hh];

    // pass 1a: per-head max
    float mxv[H];
    #pragma unroll
    for (int hh = 0; hh < H; hh++) mxv[hh] = -1e30f;
    for (int i = beg + lane; i < end; i += 32) {
        int s = g_csr[i];
        #pragma unroll
        for (int hh = 0; hh < H; hh++) {
            float e = als[s * H + hh] + aldh[hh];
            e = e > 0.f ? e : 0.2f * e;
            mxv[hh] = fmaxf(mxv[hh], e);
        }
    }
    #pragma unroll
    for (int hh = 0; hh < H; hh++)
        #pragma unroll
        for (int o = 16; o > 0; o >>= 1)
            mxv[hh] = fmaxf(mxv[hh], __shfl_xor_sync(0xffffffffu, mxv[hh], o));

    // pass 1b: per-head sum of exp
    float sv[H];
    #pragma unroll
    for (int hh = 0; hh < H; hh++) sv[hh] = 0.f;
    for (int i = beg + lane; i < end; i += 32) {
        int s = g_csr[i];
        #pragma unroll
        for (int hh = 0; hh < H; hh++) {
            float e = als[s * H + hh] + aldh[hh];
            e = e > 0.f ? e : 0.2f * e;
            sv[hh] += __expf(e - mxv[hh]);
        }
    }
    #pragma unroll
    for (int hh = 0; hh < H; hh++)
        #pragma unroll
        for (int o = 16; o > 0; o >>= 1)
            sv[hh] += __shfl_xor_sync(0xffffffffu, sv[hh], o);

    // lane < H will compute weights for head == lane
    float selM = 0.f, selI = 0.f, selA = 0.f;
    #pragma unroll
    for (int hh = 0; hh < H; hh++)
        if (hh == lane) { selM = mxv[hh]; selI = 1.f / sv[hh]; selA = aldh[hh]; }

    int hr[RPL];
    #pragma unroll
    for (int r = 0; r < RPL; r++) {
        int ch = lane + 32 * r;
        if (ch >= F) ch = F - 1;
        hr[r] = ch / C;
    }

    // pass 2: weighted gather-accumulate
    float acc[RPL];
    #pragma unroll
    for (int r = 0; r < RPL; r++) acc[r] = 0.f;

    for (int i = beg; i < end; i++) {
        int s = g_csr[i];  // uniform across warp -> broadcast
        float w = 0.f;
        if (lane < H) {
            float e = als[s * H + lane] + selA;
            e = e > 0.f ? e : 0.2f * e;
            w = __expf(e - selM) * selI;
        }
        size_t rb = (size_t)s * F;
        #pragma unroll
        for (int r = 0; r < RPL; r++) {
            float wc = __shfl_sync(0xffffffffu, w, hr[r]);
            int ch = lane + 32 * r;
            if (F % 32 == 0 || ch < F) acc[r] = fmaf(wc, __ldg(&h[rb + ch]), acc[r]);
        }
    }

    #pragma unroll
    for (int r = 0; r < RPL; r++) {
        int ch = lane + 32 * r;
        if (F % 32 == 0 || ch < F) {
            if (FUSE_BIAS_ELU) {
                float v = acc[r] + bias[ch];
                v = v > 0.f ? v : (__expf(v) - 1.f);
                out[(size_t)gw * F + ch] = v;
            } else {
                out[(size_t)gw * F + ch] = acc[r];
            }
        }
    }
}

// ---------------- final: head-mean + bias + elu + log_softmax ----------------
__global__ void final_kernel(const float* __restrict__ agg, const float* __restrict__ b3,
                             float* __restrict__ out) {
    int gw = (blockIdx.x * blockDim.x + threadIdx.x) >> 5;
    if (gw >= N_NODES) return;
    int lane = threadIdx.x & 31;
    size_t base = (size_t)gw * 240;
    const float inv6 = 1.f / 6.f;
    float t0 = 0.f, t1 = 0.f;
    #pragma unroll
    for (int hh = 0; hh < 6; hh++) {
        t0 += agg[base + hh * 40 + lane];
        if (lane < 8) t1 += agg[base + hh * 40 + 32 + lane];
    }
    t0 = t0 * inv6 + b3[lane];
    t0 = t0 > 0.f ? t0 : (__expf(t0) - 1.f);
    if (lane < 8) {
        t1 = t1 * inv6 + b3[32 + lane];
        t1 = t1 > 0.f ? t1 : (__expf(t1) - 1.f);
    }
    float m = fmaxf(t0, lane < 8 ? t1 : -1e30f);
    #pragma unroll
    for (int o = 16; o > 0; o >>= 1) m = fmaxf(m, __shfl_xor_sync(0xffffffffu, m, o));
    float se = __expf(t0 - m) + (lane < 8 ? __expf(t1 - m) : 0.f);
    #pragma unroll
    for (int o = 16; o > 0; o >>= 1) se += __shfl_xor_sync(0xffffffffu, se, o);
    float l = __logf(se) + m;
    out[(size_t)gw * 40 + lane] = t0 - l;
    if (lane < 8) out[(size_t)gw * 40 + 32 + lane] = t1 - l;
}

// ---------------- host launcher ----------------
extern "C" void kernel_launch(void* const* d_in, const int* in_sizes, int n_in,
                              void* d_out, int out_size) {
    const float* x   = (const float*)d_in[0];
    const void*  ei  = d_in[1];
    const float* W1  = (const float*)d_in[2];
    const float* a1s = (const float*)d_in[3];
    const float* a1d = (const float*)d_in[4];
    const float* b1  = (const float*)d_in[5];
    const float* W2  = (const float*)d_in[6];
    const float* a2s = (const float*)d_in[7];
    const float* a2d = (const float*)d_in[8];
    const float* b2  = (const float*)d_in[9];
    const float* W3  = (const float*)d_in[10];
    const float* a3s = (const float*)d_in[11];
    const float* a3d = (const float*)d_in[12];
    const float* b3  = (const float*)d_in[13];
    float* out = (float*)d_out;

    // resolve device symbol addresses (host-side queries, no allocation)
    float *p_h, *p_agg, *p_als, *p_ald;
    int *p_counts, *p_cursor;
    cudaGetSymbolAddress((void**)&p_h, g_h);
    cudaGetSymbolAddress((void**)&p_agg, g_agg);
    cudaGetSymbolAddress((void**)&p_als, g_als);
    cudaGetSymbolAddress((void**)&p_ald, g_ald);
    cudaGetSymbolAddress((void**)&p_counts, g_counts);
    cudaGetSymbolAddress((void**)&p_cursor, g_cursor);

    // ---- CSR build ----
    detect_idx_kernel<<<1, 32>>>((const int*)ei);
    zero_int_kernel<<<(N_NODES + 255) / 256, 256>>>(p_counts, N_NODES);
    zero_int_kernel<<<(N_NODES + 255) / 256, 256>>>(p_cursor, N_NODES);
    count_kernel<<<(E_TOT + 255) / 256, 256>>>(ei);
    scan_kernel<<<1, 1024>>>();
    fill_kernel<<<(E_TOT + 255) / 256, 256>>>(ei);

    const int AGG_GRID = (N_NODES * 32 + 255) / 256;

    // ---- layer 1: 128 -> 4x16 concat ----
    {
        constexpr int K = 128, F = 64, BM = 128, TM = 8, TF = 8, H = 4;
        size_t smem = (size_t)(K * F + BM * (K + 1) + BM * 2 * H) * sizeof(float);
        cudaFuncSetAttribute(gemm_al_kernel<K, F, BM, TM, TF, H>,
                             cudaFuncAttributeMaxDynamicSharedMemorySize, (int)smem);
        int grid = (N_NODES + BM - 1) / BM;
        gemm_al_kernel<K, F, BM, TM, TF, H><<<grid, (BM / TM) * (F / TF), smem>>>(
            x, W1, a1s, a1d, p_h, p_als, p_ald, N_NODES);
        agg_kernel<4, 16, true><<<AGG_GRID, 256>>>(p_h, p_als, p_ald, b1, p_agg);
    }

    // ---- layer 2: 64 -> 4x16 concat ----
    {
        constexpr int K = 64, F = 64, BM = 128, TM = 8, TF = 8, H = 4;
        size_t smem = (size_t)(K * F + BM * (K + 1) + BM * 2 * H) * sizeof(float);
        cudaFuncSetAttribute(gemm_al_kernel<K, F, BM, TM, TF, H>,
                             cudaFuncAttributeMaxDynamicSharedMemorySize, (int)smem);
        int grid = (N_NODES + BM - 1) / BM;
        gemm_al_kernel<K, F, BM, TM, TF, H><<<grid, (BM / TM) * (F / TF), smem>>>(
            p_agg, W2, a2s, a2d, p_h, p_als, p_ald, N_NODES);
        agg_kernel<4, 16, true><<<AGG_GRID, 256>>>(p_h, p_als, p_ald, b2, p_agg);
    }

    // ---- layer 3: 64 -> 6x40 mean ----
    {
        constexpr int K = 64, F = 240, BM = 32, TM = 4, TF = 8, H = 6;
        size_t smem = (size_t)(K * F + BM * (K + 1) + BM * 2 * H) * sizeof(float);
        cudaFuncSetAttribute(gemm_al_kernel<K, F, BM, TM, TF, H>,
                             cudaFuncAttributeMaxDynamicSharedMemorySize, (int)smem);
        gemm_al_kernel<K, F, BM, TM, TF, H><<<444, (BM / TM) * (F / TF), smem>>>(
            p_agg, W3, a3s, a3d, p_h, p_als, p_ald, N_NODES);
        agg_kernel<6, 40, false><<<AGG_GRID, 256>>>(p_h, p_als, p_ald, nullptr, p_agg);
    }

    // ---- final: mean over heads + bias + elu + log_softmax ----
    final_kernel<<<AGG_GRID, 256>>>(p_agg, b3, out);
}

// round 2
// speedup vs baseline: 1.2700x; 1.2700x over previous
#include <cuda_runtime.h>
#include <cuda_bf16.h>
#include <cstdint>

// ---------------- problem constants ----------------
#define N_NODES 50000
#define N_EDGES 1600000
#define E_TOT   (N_EDGES + N_NODES)   // + self loops
#define F_IN    128

// ---------------- device scratch (static: no allocations allowed) ----------------
__device__ float g_h[(size_t)N_NODES * 240];    // transformed features per layer
__device__ float g_agg[(size_t)N_NODES * 64];   // aggregated output (layers 1,2)
__device__ float g_als[(size_t)N_NODES * 6];
__device__ float g_ald[(size_t)N_NODES * 6];
__device__ float g_wbuf[(size_t)E_TOT * 6];     // per-CSR-slot exp(e) values
__device__ int   g_counts[N_NODES];
__device__ int   g_cursor[N_NODES];
__device__ int   g_offsets[N_NODES + 1];
__device__ int   g_csr[E_TOT];
__device__ int   g_idx64;   // 1 if edge_index is int64, 0 if int32

// ---------------- small utility kernels ----------------
__global__ void zero_int_kernel(int* a, int n) {
    int i = blockIdx.x * blockDim.x + threadIdx.x;
    if (i < n) a[i] = 0;
}

// One warp, batched loads: if the first 256 odd 32-bit words are all zero,
// the buffer is int64 (values < 2^31, non-negative).
__global__ void detect_idx_kernel(const int* p) {
    int lane = threadIdx.x;
    int bad = 0;
    #pragma unroll
    for (int r = 0; r < 8; r++) {
        int i = lane + r * 32;
        if (p[2 * i + 1] != 0) bad = 1;
    }
    bad = __any_sync(0xffffffffu, bad);
    if (lane == 0) g_idx64 = bad ? 0 : 1;
}

__device__ __forceinline__ void load_edge(const void* ei, int i, int& src, int& dst) {
    if (i < N_EDGES) {
        if (g_idx64) {
            const long long* q = (const long long*)ei;
            src = (int)q[i];
            dst = (int)q[(size_t)N_EDGES + i];
        } else {
            const int* q = (const int*)ei;
            src = q[i];
            dst = q[N_EDGES + i];
        }
    } else {
        src = dst = i - N_EDGES;  // self loop
    }
}

__global__ void count_kernel(const void* ei) {
    int i = blockIdx.x * blockDim.x + threadIdx.x;
    if (i >= E_TOT) return;
    int src, dst;
    load_edge(ei, i, src, dst);
    atomicAdd(&g_counts[dst], 1);
}

__global__ void scan_kernel() {
    __shared__ int tsum[1024];
    const int CH = (N_NODES + 1023) / 1024;  // 49
    int tid = threadIdx.x;
    int base = tid * CH;
    int s = 0;
    for (int i = 0; i < CH; i++) {
        int idx = base + i;
        if (idx < N_NODES) s += g_counts[idx];
    }
    tsum[tid] = s;
    __syncthreads();
    for (int off = 1; off < 1024; off <<= 1) {
        int v = (tid >= off) ? tsum[tid - off] : 0;
        __syncthreads();
        tsum[tid] += v;
        __syncthreads();
    }
    int excl = tsum[tid] - s;
    for (int i = 0; i < CH; i++) {
        int idx = base + i;
        if (idx < N_NODES) {
            g_offsets[idx] = excl;
            g_cursor[idx] = excl;   // fill cursor starts at segment base
            excl += g_counts[idx];
        }
    }
    if (tid == 1023) g_offsets[N_NODES] = tsum[1023];
}

__global__ void fill_kernel(const void* ei) {
    int i = blockIdx.x * blockDim.x + threadIdx.x;
    if (i >= E_TOT) return;
    int src, dst;
    load_edge(ei, i, src, dst);
    int pos = atomicAdd(&g_cursor[dst], 1);
    g_csr[pos] = src;
}

// ---------------- fused GEMM + attention-logit kernel ----------------
template <int K, int F, int BM, int TM, int TF, int H>
__global__ void gemm_al_kernel(const float* __restrict__ X, const float* __restrict__ W,
                               const float* __restrict__ Avs, const float* __restrict__ Avd,
                               float* __restrict__ Ho, float* __restrict__ als,
                               float* __restrict__ ald, int Nn) {
    constexpr int MTH = BM / TM;
    constexpr int FTH = F / TF;
    constexpr int NTH = MTH * FTH;
    constexpr int C = F / H;
    constexpr int XLD = K + 1;
    extern __shared__ float sh[];
    float* ws = sh;                  // K*F
    float* xs = ws + K * F;          // BM*XLD
    float* asum = xs + BM * XLD;     // BM*2*H

    int tid = threadIdx.x;
    for (int i = tid; i < K * F; i += NTH) ws[i] = W[i];

    int mx = tid % MTH;
    int fx = tid / MTH;
    int f0 = fx * TF;
    int headT = f0 / C;
    float ras[TF], rad[TF];
    #pragma unroll
    for (int j = 0; j < TF; j++) { ras[j] = Avs[f0 + j]; rad[j] = Avd[f0 + j]; }

    for (int tile = blockIdx.x * BM; tile < Nn; tile += gridDim.x * BM) {
        __syncthreads();
        for (int i = tid; i < BM * K; i += NTH) {
            int m = i / K, k = i - m * K;
            int gm = tile + m;
            xs[m * XLD + k] = (gm < Nn) ? X[(size_t)gm * K + k] : 0.f;
        }
        for (int i = tid; i < BM * 2 * H; i += NTH) asum[i] = 0.f;
        __syncthreads();

        float acc[TM][TF];
        #pragma unroll
        for (int i = 0; i < TM; i++)
            #pragma unroll
            for (int j = 0; j < TF; j++) acc[i][j] = 0.f;

        #pragma unroll 4
        for (int k = 0; k < K; k++) {
            float xv[TM];
            #pragma unroll
            for (int i = 0; i < TM; i++) xv[i] = xs[(mx + i * MTH) * XLD + k];
            float wv[TF];
            #pragma unroll
            for (int j4 = 0; j4 < TF / 4; j4++) {
                float4 w4 = *reinterpret_cast<const float4*>(&ws[k * F + f0 + j4 * 4]);
                wv[j4 * 4 + 0] = w4.x; wv[j4 * 4 + 1] = w4.y;
                wv[j4 * 4 + 2] = w4.z; wv[j4 * 4 + 3] = w4.w;
            }
            #pragma unroll
            for (int i = 0; i < TM; i++)
                #pragma unroll
                for (int j = 0; j < TF; j++) acc[i][j] = fmaf(xv[i], wv[j], acc[i][j]);
        }

        #pragma unroll
        for (int i = 0; i < TM; i++) {
            int m = mx + i * MTH;
            int gm = tile + m;
            if (gm < Nn) {
                float ss = 0.f, sd = 0.f;
                #pragma unroll
                for (int j = 0; j < TF; j++) {
                    Ho[(size_t)gm * F + f0 + j] = acc[i][j];
                    ss += acc[i][j] * ras[j];
                    sd += acc[i][j] * rad[j];
                }
                atomicAdd(&asum[m * 2 * H + headT], ss);
                atomicAdd(&asum[m * 2 * H + H + headT], sd);
            }
        }
        __syncthreads();
        for (int i = tid; i < BM * H; i += NTH) {
            int m = i / H, hh = i - m * H;
            int gm = tile + m;
            if (gm < Nn) {
                als[gm * H + hh] = asum[m * 2 * H + hh];
                ald[gm * H + hh] = asum[m * 2 * H + H + hh];
            }
        }
    }
}

// ---------------- per-dst softmax aggregation: one warp per node ----------------
// MODE 0: out[n, F] = elu(agg + bias)
// MODE 1: out[n, 40] = log_softmax(elu(head_mean(agg) + bias))   (layer 3)
template <int H, int C, int MODE>
__global__ void agg_kernel(const float* __restrict__ h, const float* __restrict__ als,
                           const float* __restrict__ ald, const float* __restrict__ bias,
                           float* __restrict__ out, float* __restrict__ wbuf) {
    constexpr int F = H * C;
    constexpr int J = (F + 63) / 64;   // float2 chunks per lane
    int gw = (blockIdx.x * blockDim.x + threadIdx.x) >> 5;
    if (gw >= N_NODES) return;
    int lane = threadIdx.x & 31;
    int beg = g_offsets[gw], end = g_offsets[gw + 1];

    // ald row for this dst
    float aldh[H];
    if (H == 4) {
        float4 t = *reinterpret_cast<const float4*>(&ald[gw * 4]);
        aldh[0] = t.x; aldh[1] = t.y; aldh[2] = t.z; aldh[3] = t.w;
    } else {
        #pragma unroll
        for (int q = 0; q < H / 2; q++) {
            float2 t = *reinterpret_cast<const float2*>(&ald[gw * H + 2 * q]);
            aldh[2 * q] = t.x; aldh[2 * q + 1] = t.y;
        }
    }

    // pass 1: sum of exp(leakyrelu(e)) per head; store exp values per CSR slot.
    // No max subtraction: logits here are O(±8), exp is fp32-safe, and
    // exp(e)/sum(exp(e)) is mathematically identical to the max-shifted form.
    float sv[H];
    #pragma unroll
    for (int hh = 0; hh < H; hh++) sv[hh] = 0.f;
    for (int i = beg + lane; i < end; i += 32) {
        int s = g_csr[i];
        float av[H];
        if (H == 4) {
            float4 t = *reinterpret_cast<const float4*>(&als[s * 4]);
            av[0] = t.x; av[1] = t.y; av[2] = t.z; av[3] = t.w;
        } else {
            #pragma unroll
            for (int q = 0; q < H / 2; q++) {
                float2 t = *reinterpret_cast<const float2*>(&als[s * H + 2 * q]);
                av[2 * q] = t.x; av[2 * q + 1] = t.y;
            }
        }
        float w[H];
        #pragma unroll
        for (int hh = 0; hh < H; hh++) {
            float e = av[hh] + aldh[hh];
            e = e > 0.f ? e : 0.2f * e;
            float x = __expf(e);
            w[hh] = x;
            sv[hh] += x;
        }
        if (H == 4) {
            *reinterpret_cast<float4*>(&wbuf[(size_t)i * 4]) =
                make_float4(w[0], w[1], w[2], w[3]);
        } else {
            #pragma unroll
            for (int q = 0; q < H / 2; q++)
                *reinterpret_cast<float2*>(&wbuf[(size_t)i * H + 2 * q]) =
                    make_float2(w[2 * q], w[2 * q + 1]);
        }
    }
    #pragma unroll
    for (int hh = 0; hh < H; hh++)
        #pragma unroll
        for (int o = 16; o > 0; o >>= 1)
            sv[hh] += __shfl_xor_sync(0xffffffffu, sv[hh], o);

    // per-lane channel chunks: ch_j = j*64 + lane*2 (ch and ch+1 share a head)
    int hr[J];
    float inv[J];
    #pragma unroll
    for (int j = 0; j < J; j++) {
        int ch = j * 64 + lane * 2;
        if (ch >= F) ch = F - 2;
        hr[j] = ch / C;
        float sel = sv[0];
        #pragma unroll
        for (int hh = 1; hh < H; hh++)
            if (hr[j] == hh) sel = sv[hh];
        inv[j] = 1.f / sel;
    }

    // pass 2: weighted gather-accumulate (float2, broadcast weight loads)
    float2 acc[J];
    #pragma unroll
    for (int j = 0; j < J; j++) acc[j] = make_float2(0.f, 0.f);

    #pragma unroll 2
    for (int i = beg; i < end; i++) {
        int s = g_csr[i];                 // uniform across warp -> broadcast
        size_t rb = (size_t)s * F;
        #pragma unroll
        for (int j = 0; j < J; j++) {
            int ch = j * 64 + lane * 2;
            if (F % 64 == 0 || ch < F) {
                float wv = __ldg(&wbuf[(size_t)i * H + hr[j]]) * inv[j];
                float2 hv = *reinterpret_cast<const float2*>(&h[rb + ch]);
                acc[j].x = fmaf(wv, hv.x, acc[j].x);
                acc[j].y = fmaf(wv, hv.y, acc[j].y);
            }
        }
    }

    if (MODE == 0) {
        // bias + ELU, write [n, F]
        #pragma unroll
        for (int j = 0; j < J; j++) {
            int ch = j * 64 + lane * 2;
            float vx = acc[j].x + bias[ch];
            float vy = acc[j].y + bias[ch + 1];
            vx = vx > 0.f ? vx : (__expf(vx) - 1.f);
            vy = vy > 0.f ? vy : (__expf(vy) - 1.f);
            *reinterpret_cast<float2*>(&out[(size_t)gw * F + ch]) = make_float2(vx, vy);
        }
    } else {
        // head-mean + bias + ELU + log_softmax, write [n, 40]
        __shared__ float sm[8][240];
        int wi = threadIdx.x >> 5;
        #pragma unroll
        for (int j = 0; j < J; j++) {
            int ch = j * 64 + lane * 2;
            if (ch < F) { sm[wi][ch] = acc[j].x; sm[wi][ch + 1] = acc[j].y; }
        }
        __syncwarp();
        const float inv6 = 1.f / 6.f;
        float t0 = 0.f, t1 = 0.f;
        #pragma unroll
        for (int hh = 0; hh < 6; hh++) {
            t0 += sm[wi][hh * 40 + lane];
            if (lane < 8) t1 += sm[wi][hh * 40 + 32 + lane];
        }
        t0 = t0 * inv6 + bias[lane];
        t0 = t0 > 0.f ? t0 : (__expf(t0) - 1.f);
        if (lane < 8) {
            t1 = t1 * inv6 + bias[32 + lane];
            t1 = t1 > 0.f ? t1 : (__expf(t1) - 1.f);
        }
        float m = fmaxf(t0, lane < 8 ? t1 : -1e30f);
        #pragma unroll
        for (int o = 16; o > 0; o >>= 1) m = fmaxf(m, __shfl_xor_sync(0xffffffffu, m, o));
        float se = __expf(t0 - m) + (lane < 8 ? __expf(t1 - m) : 0.f);
        #pragma unroll
        for (int o = 16; o > 0; o >>= 1) se += __shfl_xor_sync(0xffffffffu, se, o);
        float l = __logf(se) + m;
        out[(size_t)gw * 40 + lane] = t0 - l;
        if (lane < 8) out[(size_t)gw * 40 + 32 + lane] = t1 - l;
    }
}

// ---------------- host launcher ----------------
extern "C" void kernel_launch(void* const* d_in, const int* in_sizes, int n_in,
                              void* d_out, int out_size) {
    const float* x   = (const float*)d_in[0];
    const void*  ei  = d_in[1];
    const float* W1  = (const float*)d_in[2];
    const float* a1s = (const float*)d_in[3];
    const float* a1d = (const float*)d_in[4];
    const float* b1  = (const float*)d_in[5];
    const float* W2  = (const float*)d_in[6];
    const float* a2s = (const float*)d_in[7];
    const float* a2d = (const float*)d_in[8];
    const float* b2  = (const float*)d_in[9];
    const float* W3  = (const float*)d_in[10];
    const float* a3s = (const float*)d_in[11];
    const float* a3d = (const float*)d_in[12];
    const float* b3  = (const float*)d_in[13];
    float* out = (float*)d_out;

    float *p_h, *p_agg, *p_als, *p_ald, *p_wbuf;
    int *p_counts;
    cudaGetSymbolAddress((void**)&p_h, g_h);
    cudaGetSymbolAddress((void**)&p_agg, g_agg);
    cudaGetSymbolAddress((void**)&p_als, g_als);
    cudaGetSymbolAddress((void**)&p_ald, g_ald);
    cudaGetSymbolAddress((void**)&p_wbuf, g_wbuf);
    cudaGetSymbolAddress((void**)&p_counts, g_counts);

    // ---- CSR build ----
    detect_idx_kernel<<<1, 32>>>((const int*)ei);
    zero_int_kernel<<<(N_NODES + 255) / 256, 256>>>(p_counts, N_NODES);
    count_kernel<<<(E_TOT + 255) / 256, 256>>>(ei);
    scan_kernel<<<1, 1024>>>();
    fill_kernel<<<(E_TOT + 255) / 256, 256>>>(ei);

    const int AGG_GRID = (N_NODES * 32 + 255) / 256;

    // ---- layer 1: 128 -> 4x16 concat ----
    {
        constexpr int K = 128, F = 64, BM = 128, TM = 8, TF = 8, H = 4;
        size_t smem = (size_t)(K * F + BM * (K + 1) + BM * 2 * H) * sizeof(float);
        cudaFuncSetAttribute(gemm_al_kernel<K, F, BM, TM, TF, H>,
                             cudaFuncAttributeMaxDynamicSharedMemorySize, (int)smem);
        int grid = (N_NODES + BM - 1) / BM;
        gemm_al_kernel<K, F, BM, TM, TF, H><<<grid, (BM / TM) * (F / TF), smem>>>(
            x, W1, a1s, a1d, p_h, p_als, p_ald, N_NODES);
        agg_kernel<4, 16, 0><<<AGG_GRID, 256>>>(p_h, p_als, p_ald, b1, p_agg, p_wbuf);
    }

    // ---- layer 2: 64 -> 4x16 concat ----
    {
        constexpr int K = 64, F = 64, BM = 128, TM = 8, TF = 8, H = 4;
        size_t smem = (size_t)(K * F + BM * (K + 1) + BM * 2 * H) * sizeof(float);
        cudaFuncSetAttribute(gemm_al_kernel<K, F, BM, TM, TF, H>,
                             cudaFuncAttributeMaxDynamicSharedMemorySize, (int)smem);
        int grid = (N_NODES + BM - 1) / BM;
        gemm_al_kernel<K, F, BM, TM, TF, H><<<grid, (BM / TM) * (F / TF), smem>>>(
            p_agg, W2, a2s, a2d, p_h, p_als, p_ald, N_NODES);
        agg_kernel<4, 16, 0><<<AGG_GRID, 256>>>(p_h, p_als, p_ald, b2, p_agg, p_wbuf);
    }

    // ---- layer 3: 64 -> 6x40 mean + fused final ----
    {
        constexpr int K = 64, F = 240, BM = 128, TM = 8, TF = 8, H = 6;
        size_t smem = (size_t)(K * F + BM * (K + 1) + BM * 2 * H) * sizeof(float);
        cudaFuncSetAttribute(gemm_al_kernel<K, F, BM, TM, TF, H>,
                             cudaFuncAttributeMaxDynamicSharedMemorySize, (int)smem);
        int grid = (N_NODES + BM - 1) / BM;
        gemm_al_kernel<K, F, BM, TM, TF, H><<<grid, (BM / TM) * (F / TF), smem>>>(
            p_agg, W3, a3s, a3d, p_h, p_als, p_ald, N_NODES);
        agg_kernel<6, 40, 1><<<AGG_GRID, 256>>>(p_h, p_als, p_ald, b3, out, p_wbuf);
    }
}

// round 3
// speedup vs baseline: 1.4633x; 1.1522x over previous
#include <cuda_runtime.h>
#include <cuda_bf16.h>
#include <cstdint>

// ---------------- problem constants ----------------
#define N_NODES 50000
#define N_EDGES 1600000
#define E_TOT   (N_EDGES + N_NODES)   // + self loops
#define F_IN    128

#define SCAN_B   256
#define SCAN_NB  ((N_NODES + SCAN_B - 1) / SCAN_B)   // 196

// ---------------- device scratch (static: no allocations allowed) ----------------
__device__ float g_h[(size_t)N_NODES * 240];    // transformed features per layer
__device__ float g_agg[(size_t)N_NODES * 64];   // aggregated output (layers 1,2)
__device__ float g_als[(size_t)N_NODES * 6];
__device__ float g_ald[(size_t)N_NODES * 6];
__device__ float g_wbuf[(size_t)E_TOT * 6];     // per-CSR-slot exp(e) values
__device__ int   g_counts[N_NODES];
__device__ int   g_cursor[N_NODES];
__device__ int   g_offsets[N_NODES + 1];
__device__ int   g_csr[E_TOT];
__device__ int   g_bsum[SCAN_NB];
__device__ int   g_bpre[SCAN_NB];
__device__ int   g_idx64;   // 1 if edge_index is int64, 0 if int32

// ---------------- dtype detect ----------------
__global__ void detect_idx_kernel(const int* p) {
    int lane = threadIdx.x;
    int bad = 0;
    #pragma unroll
    for (int r = 0; r < 8; r++) {
        int i = lane + r * 32;
        if (p[2 * i + 1] != 0) bad = 1;
    }
    bad = __any_sync(0xffffffffu, bad);
    if (lane == 0) g_idx64 = bad ? 0 : 1;
}

__device__ __forceinline__ void load_edge(const void* ei, int i, int& src, int& dst) {
    if (i < N_EDGES) {
        if (g_idx64) {
            const long long* q = (const long long*)ei;
            src = (int)q[i];
            dst = (int)q[(size_t)N_EDGES + i];
        } else {
            const int* q = (const int*)ei;
            src = q[i];
            dst = q[N_EDGES + i];
        }
    } else {
        src = dst = i - N_EDGES;  // self loop
    }
}

__global__ void count_kernel(const void* ei) {
    int i = blockIdx.x * blockDim.x + threadIdx.x;
    if (i >= E_TOT) return;
    int src, dst;
    load_edge(ei, i, src, dst);
    atomicAdd(&g_counts[dst], 1);
}

// ---------------- 3-stage parallel exclusive scan over g_counts ----------------
__global__ void bsum_kernel() {
    int b = blockIdx.x, t = threadIdx.x;
    int idx = b * SCAN_B + t;
    int v = (idx < N_NODES) ? g_counts[idx] : 0;
    #pragma unroll
    for (int o = 16; o > 0; o >>= 1) v += __shfl_xor_sync(0xffffffffu, v, o);
    __shared__ int ws[SCAN_B / 32];
    if ((t & 31) == 0) ws[t >> 5] = v;
    __syncthreads();
    if (t < SCAN_B / 32) {
        int s = ws[t];
        #pragma unroll
        for (int o = SCAN_B / 64; o > 0; o >>= 1) s += __shfl_xor_sync(0xffu, s, o);
        if (t == 0) g_bsum[b] = s;
    }
}

__global__ void bscan_kernel() {
    __shared__ int sm[SCAN_B];
    int t = threadIdx.x;
    int v = (t < SCAN_NB) ? g_bsum[t] : 0;
    sm[t] = v;
    __syncthreads();
    #pragma unroll
    for (int off = 1; off < SCAN_B; off <<= 1) {
        int u = (t >= off) ? sm[t - off] : 0;
        __syncthreads();
        sm[t] += u;
        __syncthreads();
    }
    if (t < SCAN_NB) g_bpre[t] = sm[t] - v;   // exclusive
}

__global__ void offsets_kernel() {
    __shared__ int sm[SCAN_B];
    int b = blockIdx.x, t = threadIdx.x;
    int idx = b * SCAN_B + t;
    int v = (idx < N_NODES) ? g_counts[idx] : 0;
    sm[t] = v;
    __syncthreads();
    #pragma unroll
    for (int off = 1; off < SCAN_B; off <<= 1) {
        int u = (t >= off) ? sm[t - off] : 0;
        __syncthreads();
        sm[t] += u;
        __syncthreads();
    }
    int excl = sm[t] - v + g_bpre[b];
    if (idx < N_NODES) {
        g_offsets[idx] = excl;
        g_cursor[idx] = excl;
    }
    if (idx == 0) g_offsets[N_NODES] = E_TOT;  // total is exact by construction
}

__global__ void fill_kernel(const void* ei) {
    int i = blockIdx.x * blockDim.x + threadIdx.x;
    if (i >= E_TOT) return;
    int src, dst;
    load_edge(ei, i, src, dst);
    int pos = atomicAdd(&g_cursor[dst], 1);
    g_csr[pos] = src;
}

// ---------------- fused GEMM + attention-logit kernel ----------------
template <int K, int F, int BM, int TM, int TF, int H>
__global__ void gemm_al_kernel(const float* __restrict__ X, const float* __restrict__ W,
                               const float* __restrict__ Avs, const float* __restrict__ Avd,
                               float* __restrict__ Ho, float* __restrict__ als,
                               float* __restrict__ ald, int Nn) {
    constexpr int MTH = BM / TM;
    constexpr int FTH = F / TF;
    constexpr int NTH = MTH * FTH;
    constexpr int C = F / H;
    constexpr int XLD = K + 1;
    extern __shared__ float sh[];
    float* ws = sh;                  // K*F
    float* xs = ws + K * F;          // BM*XLD
    float* asum = xs + BM * XLD;     // BM*2*H

    int tid = threadIdx.x;
    for (int i = tid; i < K * F; i += NTH) ws[i] = W[i];

    int mx = tid % MTH;
    int fx = tid / MTH;
    int f0 = fx * TF;
    int headT = f0 / C;
    float ras[TF], rad[TF];
    #pragma unroll
    for (int j = 0; j < TF; j++) { ras[j] = Avs[f0 + j]; rad[j] = Avd[f0 + j]; }

    for (int tile = blockIdx.x * BM; tile < Nn; tile += gridDim.x * BM) {
        __syncthreads();
        for (int i = tid; i < BM * K; i += NTH) {
            int m = i / K, k = i - m * K;
            int gm = tile + m;
            xs[m * XLD + k] = (gm < Nn) ? X[(size_t)gm * K + k] : 0.f;
        }
        for (int i = tid; i < BM * 2 * H; i += NTH) asum[i] = 0.f;
        __syncthreads();

        float acc[TM][TF];
        #pragma unroll
        for (int i = 0; i < TM; i++)
            #pragma unroll
            for (int j = 0; j < TF; j++) acc[i][j] = 0.f;

        #pragma unroll 4
        for (int k = 0; k < K; k++) {
            float xv[TM];
            #pragma unroll
            for (int i = 0; i < TM; i++) xv[i] = xs[(mx + i * MTH) * XLD + k];
            float wv[TF];
            #pragma unroll
            for (int j4 = 0; j4 < TF / 4; j4++) {
                float4 w4 = *reinterpret_cast<const float4*>(&ws[k * F + f0 + j4 * 4]);
                wv[j4 * 4 + 0] = w4.x; wv[j4 * 4 + 1] = w4.y;
                wv[j4 * 4 + 2] = w4.z; wv[j4 * 4 + 3] = w4.w;
            }
            #pragma unroll
            for (int i = 0; i < TM; i++)
                #pragma unroll
                for (int j = 0; j < TF; j++) acc[i][j] = fmaf(xv[i], wv[j], acc[i][j]);
        }

        #pragma unroll
        for (int i = 0; i < TM; i++) {
            int m = mx + i * MTH;
            int gm = tile + m;
            if (gm < Nn) {
                float ss = 0.f, sd = 0.f;
                #pragma unroll
                for (int j = 0; j < TF; j++) {
                    Ho[(size_t)gm * F + f0 + j] = acc[i][j];
                    ss += acc[i][j] * ras[j];
                    sd += acc[i][j] * rad[j];
                }
                atomicAdd(&asum[m * 2 * H + headT], ss);
                atomicAdd(&asum[m * 2 * H + H + headT], sd);
            }
        }
        __syncthreads();
        for (int i = tid; i < BM * H; i += NTH) {
            int m = i / H, hh = i - m * H;
            int gm = tile + m;
            if (gm < Nn) {
                als[gm * H + hh] = asum[m * 2 * H + hh];
                ald[gm * H + hh] = asum[m * 2 * H + H + hh];
            }
        }
    }
}

// ---------------- per-dst softmax aggregation: one warp per node ----------------
// MODE 0: out[n, F] = elu(agg + bias)
// MODE 1: out[n, 40] = log_softmax(elu(head_mean(agg) + bias))   (layer 3)
template <int H, int C, int MODE>
__global__ void agg_kernel(const float* __restrict__ h, const float* __restrict__ als,
                           const float* __restrict__ ald, const float* __restrict__ bias,
                           float* __restrict__ out, float* __restrict__ wbuf) {
    constexpr int F = H * C;
    constexpr int J = (F + 63) / 64;   // float2 chunks per lane
    int gw = (blockIdx.x * blockDim.x + threadIdx.x) >> 5;
    if (gw >= N_NODES) return;
    int lane = threadIdx.x & 31;
    int beg = g_offsets[gw], end = g_offsets[gw + 1];

    float aldh[H];
    if (H == 4) {
        float4 t = *reinterpret_cast<const float4*>(&ald[gw * 4]);
        aldh[0] = t.x; aldh[1] = t.y; aldh[2] = t.z; aldh[3] = t.w;
    } else {
        #pragma unroll
        for (int q = 0; q < H / 2; q++) {
            float2 t = *reinterpret_cast<const float2*>(&ald[gw * H + 2 * q]);
            aldh[2 * q] = t.x; aldh[2 * q + 1] = t.y;
        }
    }

    // pass 1: sum of exp(leakyrelu(e)) per head; store exp values per CSR slot.
    float sv[H];
    #pragma unroll
    for (int hh = 0; hh < H; hh++) sv[hh] = 0.f;
    for (int i = beg + lane; i < end; i += 32) {
        int s = g_csr[i];
        float av[H];
        if (H == 4) {
            float4 t = *reinterpret_cast<const float4*>(&als[s * 4]);
            av[0] = t.x; av[1] = t.y; av[2] = t.z; av[3] = t.w;
        } else {
            #pragma unroll
            for (int q = 0; q < H / 2; q++) {
                float2 t = *reinterpret_cast<const float2*>(&als[s * H + 2 * q]);
                av[2 * q] = t.x; av[2 * q + 1] = t.y;
            }
        }
        float w[H];
        #pragma unroll
        for (int hh = 0; hh < H; hh++) {
            float e = av[hh] + aldh[hh];
            e = e > 0.f ? e : 0.2f * e;
            float x = __expf(e);
            w[hh] = x;
            sv[hh] += x;
        }
        if (H == 4) {
            *reinterpret_cast<float4*>(&wbuf[(size_t)i * 4]) =
                make_float4(w[0], w[1], w[2], w[3]);
        } else {
            #pragma unroll
            for (int q = 0; q < H / 2; q++)
                *reinterpret_cast<float2*>(&wbuf[(size_t)i * H + 2 * q]) =
                    make_float2(w[2 * q], w[2 * q + 1]);
        }
    }
    #pragma unroll
    for (int hh = 0; hh < H; hh++)
        #pragma unroll
        for (int o = 16; o > 0; o >>= 1)
            sv[hh] += __shfl_xor_sync(0xffffffffu, sv[hh], o);

    int hr[J];
    float inv[J];
    #pragma unroll
    for (int j = 0; j < J; j++) {
        int ch = j * 64 + lane * 2;
        if (ch >= F) ch = F - 2;
        hr[j] = ch / C;
        float sel = sv[0];
        #pragma unroll
        for (int hh = 1; hh < H; hh++)
            if (hr[j] == hh) sel = sv[hh];
        inv[j] = 1.f / sel;
    }

    // pass 2: weighted gather-accumulate (float2, broadcast weight loads)
    float2 acc[J];
    #pragma unroll
    for (int j = 0; j < J; j++) acc[j] = make_float2(0.f, 0.f);

    #pragma unroll 2
    for (int i = beg; i < end; i++) {
        int s = g_csr[i];                 // uniform across warp -> broadcast
        size_t rb = (size_t)s * F;
        #pragma unroll
        for (int j = 0; j < J; j++) {
            int ch = j * 64 + lane * 2;
            if (F % 64 == 0 || ch < F) {
                float wv = __ldg(&wbuf[(size_t)i * H + hr[j]]) * inv[j];
                float2 hv = *reinterpret_cast<const float2*>(&h[rb + ch]);
                acc[j].x = fmaf(wv, hv.x, acc[j].x);
                acc[j].y = fmaf(wv, hv.y, acc[j].y);
            }
        }
    }

    if (MODE == 0) {
        #pragma unroll
        for (int j = 0; j < J; j++) {
            int ch = j * 64 + lane * 2;
            float vx = acc[j].x + bias[ch];
            float vy = acc[j].y + bias[ch + 1];
            vx = vx > 0.f ? vx : (__expf(vx) - 1.f);
            vy = vy > 0.f ? vy : (__expf(vy) - 1.f);
            *reinterpret_cast<float2*>(&out[(size_t)gw * F + ch]) = make_float2(vx, vy);
        }
    } else {
        __shared__ float sm[8][240];
        int wi = threadIdx.x >> 5;
        #pragma unroll
        for (int j = 0; j < J; j++) {
            int ch = j * 64 + lane * 2;
            if (ch < F) { sm[wi][ch] = acc[j].x; sm[wi][ch + 1] = acc[j].y; }
        }
        __syncwarp();
        const float inv6 = 1.f / 6.f;
        float t0 = 0.f, t1 = 0.f;
        #pragma unroll
        for (int hh = 0; hh < 6; hh++) {
            t0 += sm[wi][hh * 40 + lane];
            if (lane < 8) t1 += sm[wi][hh * 40 + 32 + lane];
        }
        t0 = t0 * inv6 + bias[lane];
        t0 = t0 > 0.f ? t0 : (__expf(t0) - 1.f);
        if (lane < 8) {
            t1 = t1 * inv6 + bias[32 + lane];
            t1 = t1 > 0.f ? t1 : (__expf(t1) - 1.f);
        }
        float m = fmaxf(t0, lane < 8 ? t1 : -1e30f);
        #pragma unroll
        for (int o = 16; o > 0; o >>= 1) m = fmaxf(m, __shfl_xor_sync(0xffffffffu, m, o));
        float se = __expf(t0 - m) + (lane < 8 ? __expf(t1 - m) : 0.f);
        #pragma unroll
        for (int o = 16; o > 0; o >>= 1) se += __shfl_xor_sync(0xffffffffu, se, o);
        float l = __logf(se) + m;
        out[(size_t)gw * 40 + lane] = t0 - l;
        if (lane < 8) out[(size_t)gw * 40 + 32 + lane] = t1 - l;
    }
}

// ---------------- host launcher ----------------
extern "C" void kernel_launch(void* const* d_in, const int* in_sizes, int n_in,
                              void* d_out, int out_size) {
    const float* x   = (const float*)d_in[0];
    const void*  ei  = d_in[1];
    const float* W1  = (const float*)d_in[2];
    const float* a1s = (const float*)d_in[3];
    const float* a1d = (const float*)d_in[4];
    const float* b1  = (const float*)d_in[5];
    const float* W2  = (const float*)d_in[6];
    const float* a2s = (const float*)d_in[7];
    const float* a2d = (const float*)d_in[8];
    const float* b2  = (const float*)d_in[9];
    const float* W3  = (const float*)d_in[10];
    const float* a3s = (const float*)d_in[11];
    const float* a3d = (const float*)d_in[12];
    const float* b3  = (const float*)d_in[13];
    float* out = (float*)d_out;

    float *p_h, *p_agg, *p_als, *p_ald, *p_wbuf;
    int *p_counts;
    cudaGetSymbolAddress((void**)&p_h, g_h);
    cudaGetSymbolAddress((void**)&p_agg, g_agg);
    cudaGetSymbolAddress((void**)&p_als, g_als);
    cudaGetSymbolAddress((void**)&p_ald, g_ald);
    cudaGetSymbolAddress((void**)&p_wbuf, g_wbuf);
    cudaGetSymbolAddress((void**)&p_counts, g_counts);

    // ---- CSR build ----
    detect_idx_kernel<<<1, 32>>>((const int*)ei);
    cudaMemsetAsync(p_counts, 0, N_NODES * sizeof(int));
    count_kernel<<<(E_TOT + 255) / 256, 256>>>(ei);
    bsum_kernel<<<SCAN_NB, SCAN_B>>>();
    bscan_kernel<<<1, SCAN_B>>>();
    offsets_kernel<<<SCAN_NB, SCAN_B>>>();
    fill_kernel<<<(E_TOT + 255) / 256, 256>>>(ei);

    const int AGG_GRID = (N_NODES * 32 + 255) / 256;

    // ---- layer 1: 128 -> 4x16 concat ----
    {
        constexpr int K = 128, F = 64, BM = 128, TM = 8, TF = 8, H = 4;
        size_t smem = (size_t)(K * F + BM * (K + 1) + BM * 2 * H) * sizeof(float);
        cudaFuncSetAttribute(gemm_al_kernel<K, F, BM, TM, TF, H>,
                             cudaFuncAttributeMaxDynamicSharedMemorySize, (int)smem);
        int grid = (N_NODES + BM - 1) / BM;
        gemm_al_kernel<K, F, BM, TM, TF, H><<<grid, (BM / TM) * (F / TF), smem>>>(
            x, W1, a1s, a1d, p_h, p_als, p_ald, N_NODES);
        agg_kernel<4, 16, 0><<<AGG_GRID, 256>>>(p_h, p_als, p_ald, b1, p_agg, p_wbuf);
    }

    // ---- layer 2: 64 -> 4x16 concat ----
    {
        constexpr int K = 64, F = 64, BM = 128, TM = 8, TF = 8, H = 4;
        size_t smem = (size_t)(K * F + BM * (K + 1) + BM * 2 * H) * sizeof(float);
        cudaFuncSetAttribute(gemm_al_kernel<K, F, BM, TM, TF, H>,
                             cudaFuncAttributeMaxDynamicSharedMemorySize, (int)smem);
        int grid = (N_NODES + BM - 1) / BM;
        gemm_al_kernel<K, F, BM, TM, TF, H><<<grid, (BM / TM) * (F / TF), smem>>>(
            p_agg, W2, a2s, a2d, p_h, p_als, p_ald, N_NODES);
        agg_kernel<4, 16, 0><<<AGG_GRID, 256>>>(p_h, p_als, p_ald, b2, p_agg, p_wbuf);
    }

    // ---- layer 3: 64 -> 6x40 mean + fused final ----
    {
        constexpr int K = 64, F = 240, BM = 128, TM = 8, TF = 8, H = 6;
        size_t smem = (size_t)(K * F + BM * (K + 1) + BM * 2 * H) * sizeof(float);
        cudaFuncSetAttribute(gemm_al_kernel<K, F, BM, TM, TF, H>,
                             cudaFuncAttributeMaxDynamicSharedMemorySize, (int)smem);
        int grid = (N_NODES + BM - 1) / BM;
        gemm_al_kernel<K, F, BM, TM, TF, H><<<grid, (BM / TM) * (F / TF), smem>>>(
            p_agg, W3, a3s, a3d, p_h, p_als, p_ald, N_NODES);
        agg_kernel<6, 40, 1><<<AGG_GRID, 256>>>(p_h, p_als, p_ald, b3, out, p_wbuf);
    }
}